// round 10
// baseline (speedup 1.0000x reference)
#include <cuda_runtime.h>
#include <cuda_fp16.h>
#include <math.h>
#include <stdint.h>

// ---------------------------------------------------------------------------
// Problem constants (B=8, N=5376, Cin=384, Ch=768, H=W=32, n=256)
// ---------------------------------------------------------------------------
#define BB      8
#define NTOK    5376
#define CIN     384
#define CH      768
#define CH4     (CH / 4)             // 192 4-channel groups
#define MROWS   (BB * NTOK)          // 43008
#define NCHUNK  21                   // 16 (s0) + 4 (s1) + 1 (s2), 256 tokens each

// ---------------------------------------------------------------------------
// Scratch (device globals; no runtime allocation)
// ---------------------------------------------------------------------------
__device__ uint32_t g_xh [(size_t)MROWS * CIN / 2];   // x as half pairs along K
__device__ __half   g_h1h[(size_t)MROWS * CH];        // fc1 output, half
__device__ __half   g_hch[(size_t)MROWS * CH];        // dwconv out -> gelu'd in place
__device__ uint32_t g_w1p[(CIN / 2) * CH];            // fc1_w pair-interleaved [k2][n]
__device__ uint32_t g_w2p[(CH / 2) * CIN];            // fc2_w pair-interleaved [k2][n]
__device__ float    g_psum[BB * NCHUNK * CH];
__device__ float    g_pmax[BB * NCHUNK * CH];
__device__ float    g_scale[24 * CH];

// ---------------------------------------------------------------------------
// Helpers
// ---------------------------------------------------------------------------
__device__ __forceinline__ uint32_t smem_u32(const void* p) {
    uint32_t a;
    asm("{ .reg .u64 t; cvta.to.shared.u64 t, %1; cvt.u32.u64 %0, t; }"
        : "=r"(a) : "l"(p));
    return a;
}
__device__ __forceinline__ void cp16(uint32_t d, const void* s) {
    asm volatile("cp.async.cg.shared.global [%0], [%1], 16;\n" :: "r"(d), "l"(s));
}
__device__ __forceinline__ uint32_t pack_h2(float a, float b) {
    __half2 h = __floats2half2_rn(a, b);
    return *(uint32_t*)&h;
}
__device__ __forceinline__ void mma_f16(float& d0, float& d1, float& d2, float& d3,
                                        uint32_t a0, uint32_t a1, uint32_t a2, uint32_t a3,
                                        uint32_t b0, uint32_t b1) {
    asm volatile(
        "mma.sync.aligned.m16n8k16.row.col.f32.f16.f16.f32 "
        "{%0,%1,%2,%3}, {%4,%5,%6,%7}, {%8,%9}, {%0,%1,%2,%3};\n"
        : "+f"(d0), "+f"(d1), "+f"(d2), "+f"(d3)
        : "r"(a0), "r"(a1), "r"(a2), "r"(a3), "r"(b0), "r"(b1));
}
__device__ __forceinline__ void ldsm_x4(uint32_t& r0, uint32_t& r1,
                                        uint32_t& r2, uint32_t& r3, uint32_t addr) {
    asm volatile("ldmatrix.sync.aligned.m8n8.x4.shared.b16 {%0,%1,%2,%3}, [%4];"
                 : "=r"(r0), "=r"(r1), "=r"(r2), "=r"(r3) : "r"(addr));
}

// ---------------------------------------------------------------------------
// FP16 GEMM (R8 config, proven 93us/launch): C = A @ W + bias, fp32 accum.
// 128 threads (4 warps 2x2), warp tile 64x64, BM=BN=128, BK2=16 (K=32),
// ldmatrix.x4 A-fragments, scalar-LDS B fragments, 4-stage cp.async.
// ---------------------------------------------------------------------------
#define BM 128
#define BN 128
#define BK2 16
#define AROW 20
#define BROW 136
#define STAGES 4
#define AS_STAGE (BM * AROW)
#define BS_STAGE (BK2 * BROW)
#define GEMM_SMEM ((STAGES * (AS_STAGE + BS_STAGE)) * 4)   // 75776 bytes

template<bool HALF_OUT>
__global__ void __launch_bounds__(128, 2)
gemm_f16(const uint32_t* __restrict__ A, const uint32_t* __restrict__ Wp,
         const float* __restrict__ bias, void* __restrict__ Cout,
         int N, int K2)
{
    extern __shared__ uint32_t sm[];
    uint32_t* AsBase = sm;
    uint32_t* BsBase = sm + STAGES * AS_STAGE;

    const int tid  = threadIdx.x;
    const int brow = blockIdx.y * BM;
    const int bcol = blockIdx.x * BN;

    const int lane = tid & 31;
    const int wid  = tid >> 5;
    const int g    = lane >> 2;
    const int tig  = lane & 3;
    const int wm   = wid & 1;
    const int wn   = wid >> 1;

    const uint32_t asU = smem_u32(AsBase);
    const uint32_t bsU = smem_u32(BsBase);

    float acc[4][8][4];
#pragma unroll
    for (int mt = 0; mt < 4; mt++)
#pragma unroll
        for (int nt = 0; nt < 8; nt++)
#pragma unroll
            for (int v = 0; v < 4; v++) acc[mt][nt][v] = 0.0f;

    const int KT = K2 / BK2;

    auto load_stage = [&](int st, int kt) {
        const uint32_t aD = asU + (uint32_t)(st * AS_STAGE * 4);
        const uint32_t bD = bsU + (uint32_t)(st * BS_STAGE * 4);
#pragma unroll
        for (int u = 0; u < 4; u++) {
            const int li = u * 128 + tid;
            const int r = li >> 2;
            const int c = (li & 3) * 4;
            cp16(aD + (uint32_t)((r * AROW + c) * 4),
                 A + (size_t)(brow + r) * K2 + kt * BK2 + c);
        }
#pragma unroll
        for (int u = 0; u < 4; u++) {
            const int li = u * 128 + tid;
            const int r = li >> 5;
            const int c = (li & 31) * 4;
            cp16(bD + (uint32_t)((r * BROW + c) * 4),
                 Wp + (size_t)(kt * BK2 + r) * N + bcol + c);
        }
    };

#pragma unroll
    for (int s = 0; s < STAGES - 1; s++) {
        load_stage(s, s);
        asm volatile("cp.async.commit_group;" ::: "memory");
    }

    const int lm_row  = lane & 15;
    const int lm_koff = (lane >> 4) << 2;

    for (int kt = 0; kt < KT; kt++) {
        const int cur = kt & (STAGES - 1);
        asm volatile("cp.async.wait_group 2;" ::: "memory");
        __syncthreads();

        if (kt + STAGES - 1 < KT)
            load_stage((kt + STAGES - 1) & (STAGES - 1), kt + STAGES - 1);
        asm volatile("cp.async.commit_group;" ::: "memory");

        const uint32_t  aStage = asU + (uint32_t)(cur * AS_STAGE * 4);
        const uint32_t* Bsu    = BsBase + cur * BS_STAGE;

#pragma unroll
        for (int kc = 0; kc < BK2; kc += 8) {
            uint32_t af[4][4], bf[8][2];
#pragma unroll
            for (int mt = 0; mt < 4; mt++) {
                const int r = wm * 64 + mt * 16 + lm_row;
                const uint32_t addr = aStage + (uint32_t)((r * AROW + kc + lm_koff) * 4);
                ldsm_x4(af[mt][0], af[mt][1], af[mt][2], af[mt][3], addr);
            }
#pragma unroll
            for (int nt = 0; nt < 8; nt++) {
                const int c0 = wn * 64 + nt * 8 + g;
                bf[nt][0] = Bsu[(kc + tig    ) * BROW + c0];
                bf[nt][1] = Bsu[(kc + tig + 4) * BROW + c0];
            }
#pragma unroll
            for (int mt = 0; mt < 4; mt++)
#pragma unroll
                for (int nt = 0; nt < 8; nt++)
                    mma_f16(acc[mt][nt][0], acc[mt][nt][1], acc[mt][nt][2], acc[mt][nt][3],
                            af[mt][0], af[mt][1], af[mt][2], af[mt][3],
                            bf[nt][0], bf[nt][1]);
        }
    }

    // ---- epilogue ----
#pragma unroll
    for (int nt = 0; nt < 8; nt++) {
        const int col = bcol + wn * 64 + nt * 8 + 2 * tig;
        const float b0 = bias[col];
        const float b1 = bias[col + 1];
#pragma unroll
        for (int mt = 0; mt < 4; mt++) {
            const int row0 = brow + wm * 64 + mt * 16 + g;
            if (HALF_OUT) {
                uint32_t* Ch = (uint32_t*)Cout;
                Ch[(size_t)row0 * (N / 2) + col / 2] =
                    pack_h2(acc[mt][nt][0] + b0, acc[mt][nt][1] + b1);
                Ch[(size_t)(row0 + 8) * (N / 2) + col / 2] =
                    pack_h2(acc[mt][nt][2] + b0, acc[mt][nt][3] + b1);
            } else {
                float* Cf = (float*)Cout;
                *(float2*)(Cf + (size_t)row0 * N + col) =
                    make_float2(acc[mt][nt][0] + b0, acc[mt][nt][1] + b1);
                *(float2*)(Cf + (size_t)(row0 + 8) * N + col) =
                    make_float2(acc[mt][nt][2] + b0, acc[mt][nt][3] + b1);
            }
        }
    }
}

// ---------------------------------------------------------------------------
// Fused prep: convert x -> half pairs; pack fc1_w, fc2_w pair-interleaved.
// ---------------------------------------------------------------------------
#define PREP_NX ((MROWS * CIN) / 4)
#define PREP_NP ((CIN / 2) * CH)

__global__ void __launch_bounds__(256)
prep_kernel(const float* __restrict__ x,
            const float* __restrict__ w1, const float* __restrict__ w2)
{
    const int i = blockIdx.x * 256 + threadIdx.x;
    if (i < PREP_NX) {
        float4 v = *(const float4*)(x + (size_t)i * 4);
        uint2 o;
        o.x = pack_h2(v.x, v.y);
        o.y = pack_h2(v.z, v.w);
        *(uint2*)(g_xh + (size_t)i * 2) = o;
    } else if (i < PREP_NX + PREP_NP) {
        const int j  = i - PREP_NX;
        const int k2 = j / CH;
        const int n  = j % CH;
        g_w1p[j] = pack_h2(w1[(size_t)(2 * k2) * CH + n],
                           w1[(size_t)(2 * k2 + 1) * CH + n]);
    } else if (i < PREP_NX + 2 * PREP_NP) {
        const int j  = i - PREP_NX - PREP_NP;
        const int k2 = j / CIN;
        const int n  = j % CIN;
        g_w2p[j] = pack_h2(w2[(size_t)(2 * k2) * CIN + n],
                           w2[(size_t)(2 * k2 + 1) * CIN + n]);
    }
}

// ---------------------------------------------------------------------------
// Depthwise 3x3 conv, chunked (256 tokens/CTA), 4 channels per lane (uint2),
// fp32 accumulation + per-chunk sum/max partials.
// Grid (6 chgroups, 21 chunks, 8 batches), block 256 = 32 lanes x 8 slots.
// ---------------------------------------------------------------------------
__global__ void __launch_bounds__(256)
dwconv_kernel(const float* __restrict__ dw_w, const float* __restrict__ dw_b)
{
    const int cc  = blockIdx.x;         // 0..5
    const int chk = blockIdx.y;
    const int b   = blockIdx.z;

    int s, cis;
    if (chk < 16)      { s = 0; cis = chk; }
    else if (chk < 20) { s = 1; cis = chk - 16; }
    else               { s = 2; cis = 0; }

    const int offs[3] = {0, 4096, 5120};
    const int lws[3]  = {6, 5, 4};
    const int off  = offs[s];
    const int lw   = lws[s];
    const int w    = 1 << lw;
    const int tok0 = cis * 256;

    const int tid   = threadIdx.x;
    const int lane  = tid & 31;
    const int tslot = tid >> 5;
    const int c4    = cc * 32 + lane;   // 4-channel group index (0..191)

    float wgt[4][9];
    float bk[4];
#pragma unroll
    for (int ch = 0; ch < 4; ch++) {
        const int c = 4 * c4 + ch;
#pragma unroll
        for (int i = 0; i < 9; i++) wgt[ch][i] = dw_w[c * 9 + i];
        bk[ch] = dw_b[c];
    }

    const uint2* base  = (const uint2*)g_h1h + (size_t)(b * NTOK + off) * CH4 + c4;
    uint2*       obase = (uint2*)g_hch       + (size_t)(b * NTOK + off) * CH4 + c4;

    float s0 = 0, s1 = 0, s2 = 0, s3 = 0;
    float m0 = -INFINITY, m1 = -INFINITY, m2 = -INFINITY, m3 = -INFINITY;

#pragma unroll 2
    for (int t = tslot; t < 256; t += 8) {
        const int tok = tok0 + t;
        const int y = tok >> lw;
        const int x = tok & (w - 1);
        float a0 = bk[0], a1 = bk[1], a2 = bk[2], a3 = bk[3];
#pragma unroll
        for (int ky = 0; ky < 3; ky++) {
            const int yy = y + ky - 1;
            if ((unsigned)yy < (unsigned)w) {
                const int rb = yy << lw;
#pragma unroll
                for (int kx = 0; kx < 3; kx++) {
                    const int xx = x + kx - 1;
                    if ((unsigned)xx < (unsigned)w) {
                        uint2 v = base[(size_t)(rb + xx) * CH4];
                        float2 p0 = __half22float2(*(__half2*)&v.x);
                        float2 p1 = __half22float2(*(__half2*)&v.y);
                        const int tp = ky * 3 + kx;
                        a0 += wgt[0][tp] * p0.x;
                        a1 += wgt[1][tp] * p0.y;
                        a2 += wgt[2][tp] * p1.x;
                        a3 += wgt[3][tp] * p1.y;
                    }
                }
            }
        }
        uint2 o;
        o.x = pack_h2(a0, a1);
        o.y = pack_h2(a2, a3);
        obase[(size_t)tok * CH4] = o;
        s0 += a0; s1 += a1; s2 += a2; s3 += a3;
        m0 = fmaxf(m0, a0); m1 = fmaxf(m1, a1);
        m2 = fmaxf(m2, a2); m3 = fmaxf(m3, a3);
    }

    __shared__ float4 ssum[256];
    __shared__ float4 smax[256];
    ssum[tid] = make_float4(s0, s1, s2, s3);
    smax[tid] = make_float4(m0, m1, m2, m3);
    __syncthreads();
    if (tslot == 0) {
        float4 ts = ssum[lane];
        float4 tm = smax[lane];
#pragma unroll
        for (int j = 1; j < 8; j++) {
            float4 v = ssum[j * 32 + lane];
            float4 m = smax[j * 32 + lane];
            ts.x += v.x; ts.y += v.y; ts.z += v.z; ts.w += v.w;
            tm.x = fmaxf(tm.x, m.x); tm.y = fmaxf(tm.y, m.y);
            tm.z = fmaxf(tm.z, m.z); tm.w = fmaxf(tm.w, m.w);
        }
        const size_t pb = ((size_t)b * NCHUNK + chk) * CH + 4 * c4;
        *(float4*)(g_psum + pb) = ts;
        *(float4*)(g_pmax + pb) = tm;
    }
}

// ---------------------------------------------------------------------------
// Gate softmax + SE channel gates; reduces chunk partials.
// 768 threads (one per channel), one block per (s,b).
// ---------------------------------------------------------------------------
__global__ void __launch_bounds__(768)
gate_scale_kernel(const float* __restrict__ gate_w, const float* __restrict__ gate_b,
                  const float* __restrict__ ca_w,   const float* __restrict__ ra_w)
{
    const int sb  = blockIdx.x;
    const int s   = sb >> 3;
    const int b   = sb & 7;
    const int c   = threadIdx.x;        // one channel per thread

    const int cs   = (s == 0) ? 0 : (s == 1) ? 16 : 20;
    const int nch  = (s == 0) ? 16 : (s == 1) ? 4 : 1;
    const int ntok = (s == 0) ? 4096 : (s == 1) ? 1024 : 256;

    __shared__ float pool[CH + 2];
    __shared__ float red0[768];
    __shared__ float red1[768];
    __shared__ float gw0s, gw1s;

    const size_t pb0 = ((size_t)b * NCHUNK + cs) * CH + c;
    float sum = 0.0f, mx = -INFINITY;
#pragma unroll 4
    for (int j = 0; j < nch; j++) {
        sum += g_psum[pb0 + (size_t)j * CH];
        mx = fmaxf(mx, g_pmax[pb0 + (size_t)j * CH]);
    }
    const float a = sum / (float)ntok;
    pool[c + 1] = a + mx;
    red0[c] = a * gate_w[c * 2 + 0];
    red1[c] = a * gate_w[c * 2 + 1];
    if (c == 0) { pool[0] = 0.0f; pool[CH + 1] = 0.0f; }
    __syncthreads();

    for (int sft = 512; sft > 0; sft >>= 1) {
        if (c < sft && c + sft < CH) {
            red0[c] += red0[c + sft];
            red1[c] += red1[c + sft];
        }
        __syncthreads();
    }
    if (c == 0) {
        const float l0 = red0[0] + gate_b[0];
        const float l1 = red1[0] + gate_b[1];
        const float m  = fmaxf(l0, l1);
        const float e0 = expf(l0 - m), e1 = expf(l1 - m);
        const float inv = 1.0f / (e0 + e1);
        gw0s = e0 * inv;
        gw1s = e1 * inv;
    }
    __syncthreads();

    const float c0 = ca_w[0], c1 = ca_w[1], c2 = ca_w[2];
    const float r0 = ra_w[0], r1 = ra_w[1], r2 = ra_w[2];
    const float pm = pool[c], pc = pool[c + 1], pp = pool[c + 2];
    const float cav = c0 * pm + c1 * pc + c2 * pp;
    const float rav = r0 * pm + r1 * pc + r2 * pp;
    const float cas = 1.0f / (1.0f + expf(-cav));
    const float ras = 1.0f - 1.0f / (1.0f + expf(-rav));
    g_scale[sb * CH + c] = gw0s * cas + gw1s * ras;
}

// ---------------------------------------------------------------------------
// Elementwise in place on g_hch: h <- half(gelu_exact(h * scale)), uint4/thread
// ---------------------------------------------------------------------------
__device__ __forceinline__ float gelu_exact(float v)
{
    return 0.5f * v * (1.0f + erff(v * 0.70710678118654752440f));
}

__global__ void __launch_bounds__(256)
gelu_scale_kernel()
{
    const size_t nvec = (size_t)MROWS * CH / 8;
    const size_t i = (size_t)blockIdx.x * blockDim.x + threadIdx.x;
    if (i >= nvec) return;
    const size_t e   = i * 8;
    const int    row = (int)(e / CH);
    const int    c   = (int)(e % CH);
    const int    b   = row / NTOK;
    const int    tok = row % NTOK;
    const int    s   = (tok < 4096) ? 0 : ((tok < 5120) ? 1 : 2);

    uint4 hv = *((uint4*)g_hch + i);
    const float* sp = g_scale + (s * 8 + b) * CH + c;
    float4 sc0 = *(const float4*)sp;
    float4 sc1 = *(const float4*)(sp + 4);

    float2 v0 = __half22float2(*(__half2*)&hv.x);
    float2 v1 = __half22float2(*(__half2*)&hv.y);
    float2 v2 = __half22float2(*(__half2*)&hv.z);
    float2 v3 = __half22float2(*(__half2*)&hv.w);
    uint4 o;
    o.x = pack_h2(gelu_exact(v0.x * sc0.x), gelu_exact(v0.y * sc0.y));
    o.y = pack_h2(gelu_exact(v1.x * sc0.z), gelu_exact(v1.y * sc0.w));
    o.z = pack_h2(gelu_exact(v2.x * sc1.x), gelu_exact(v2.y * sc1.y));
    o.w = pack_h2(gelu_exact(v3.x * sc1.z), gelu_exact(v3.y * sc1.w));
    *((uint4*)g_hch + i) = o;
}

// ---------------------------------------------------------------------------
// Entry point
// ---------------------------------------------------------------------------
extern "C" void kernel_launch(void* const* d_in, const int* in_sizes, int n_in,
                              void* d_out, int out_size)
{
    const float* x      = (const float*)d_in[0];
    const float* fc1_w  = (const float*)d_in[1];
    const float* fc1_b  = (const float*)d_in[2];
    const float* dw_w   = (const float*)d_in[3];
    const float* dw_b   = (const float*)d_in[4];
    const float* ca_w   = (const float*)d_in[5];
    const float* ra_w   = (const float*)d_in[6];
    const float* gate_w = (const float*)d_in[7];
    const float* gate_b = (const float*)d_in[8];
    const float* fc2_w  = (const float*)d_in[9];
    const float* fc2_b  = (const float*)d_in[10];
    float* out = (float*)d_out;

    uint32_t *xh, *w1p, *w2p;
    __half *h1h, *hch;
    cudaGetSymbolAddress((void**)&xh,  g_xh);
    cudaGetSymbolAddress((void**)&h1h, g_h1h);
    cudaGetSymbolAddress((void**)&hch, g_hch);
    cudaGetSymbolAddress((void**)&w1p, g_w1p);
    cudaGetSymbolAddress((void**)&w2p, g_w2p);

    cudaFuncSetAttribute(gemm_f16<true>,  cudaFuncAttributeMaxDynamicSharedMemorySize, GEMM_SMEM);
    cudaFuncSetAttribute(gemm_f16<false>, cudaFuncAttributeMaxDynamicSharedMemorySize, GEMM_SMEM);

    // fused prep: convert x + pack both weights
    const int prep_total = PREP_NX + 2 * PREP_NP;
    prep_kernel<<<(prep_total + 255) / 256, 256>>>(x, fc1_w, fc2_w);

    // fc1: (43008 x 384) @ (384 x 768) -> g_h1h (half)
    gemm_f16<true><<<dim3(CH / BN, MROWS / BM), 128, GEMM_SMEM>>>(
        xh, w1p, fc1_b, h1h, CH, CIN / 2);

    // depthwise conv + chunked pooled stats (4 channels/lane)
    dwconv_kernel<<<dim3(CH4 / 32, NCHUNK, BB), 256>>>(dw_w, dw_b);

    // gate softmax + SE channel gates (768 threads/block)
    gate_scale_kernel<<<24, 768>>>(gate_w, gate_b, ca_w, ra_w);

    // scale + exact GELU, in place on g_hch
    const size_t nvec = (size_t)MROWS * CH / 8;
    gelu_scale_kernel<<<(unsigned)((nvec + 255) / 256), 256>>>();

    // fc2: (43008 x 768) @ (768 x 384) + bias -> out (fp32)
    gemm_f16<false><<<dim3(CIN / BN, MROWS / BM), 128, GEMM_SMEM>>>(
        (const uint32_t*)hch, w2p, fc2_b, out, CIN, CH / 2);
}

// round 11
// speedup vs baseline: 1.1429x; 1.1429x over previous
#include <cuda_runtime.h>
#include <cuda_fp16.h>
#include <math.h>
#include <stdint.h>

// ---------------------------------------------------------------------------
// Problem constants (B=8, N=5376, Cin=384, Ch=768, H=W=32, n=256)
// ---------------------------------------------------------------------------
#define BB      8
#define NTOK    5376
#define CIN     384
#define CH      768
#define MROWS   (BB * NTOK)          // 43008
#define NCHUNK  21                   // 16 (s0) + 4 (s1) + 1 (s2), 256 tokens each

// ---------------------------------------------------------------------------
// Scratch (device globals; no runtime allocation)
// ---------------------------------------------------------------------------
__device__ uint32_t g_xh [(size_t)MROWS * CIN / 2];   // x as half pairs along K
__device__ __half   g_h1h[(size_t)MROWS * CH];        // fc1 output, half
__device__ __half   g_hch[(size_t)MROWS * CH];        // dwconv out -> gelu'd in place
__device__ uint32_t g_w1p[(CIN / 2) * CH];            // fc1_w pair-interleaved [k2][n]
__device__ uint32_t g_w2p[(CH / 2) * CIN];            // fc2_w pair-interleaved [k2][n]
__device__ float    g_psum[BB * NCHUNK * CH];
__device__ float    g_pmax[BB * NCHUNK * CH];
__device__ float    g_scale[24 * CH];

// ---------------------------------------------------------------------------
// Helpers
// ---------------------------------------------------------------------------
__device__ __forceinline__ uint32_t smem_u32(const void* p) {
    uint32_t a;
    asm("{ .reg .u64 t; cvta.to.shared.u64 t, %1; cvt.u32.u64 %0, t; }"
        : "=r"(a) : "l"(p));
    return a;
}
__device__ __forceinline__ void cp16(uint32_t d, const void* s) {
    asm volatile("cp.async.cg.shared.global [%0], [%1], 16;\n" :: "r"(d), "l"(s));
}
__device__ __forceinline__ uint32_t pack_h2(float a, float b) {
    __half2 h = __floats2half2_rn(a, b);
    return *(uint32_t*)&h;
}
__device__ __forceinline__ void mma_f16(float& d0, float& d1, float& d2, float& d3,
                                        uint32_t a0, uint32_t a1, uint32_t a2, uint32_t a3,
                                        uint32_t b0, uint32_t b1) {
    asm volatile(
        "mma.sync.aligned.m16n8k16.row.col.f32.f16.f16.f32 "
        "{%0,%1,%2,%3}, {%4,%5,%6,%7}, {%8,%9}, {%0,%1,%2,%3};\n"
        : "+f"(d0), "+f"(d1), "+f"(d2), "+f"(d3)
        : "r"(a0), "r"(a1), "r"(a2), "r"(a3), "r"(b0), "r"(b1));
}
__device__ __forceinline__ void ldsm_x4(uint32_t& r0, uint32_t& r1,
                                        uint32_t& r2, uint32_t& r3, uint32_t addr) {
    asm volatile("ldmatrix.sync.aligned.m8n8.x4.shared.b16 {%0,%1,%2,%3}, [%4];"
                 : "=r"(r0), "=r"(r1), "=r"(r2), "=r"(r3) : "r"(addr));
}

// ---------------------------------------------------------------------------
// FP16 GEMM (R8 config, proven): C = A @ W + bias, fp32 accum.
// 128 threads (4 warps 2x2), warp tile 64x64, BM=BN=128, BK2=16 (K=32),
// ldmatrix.x4 A-fragments, scalar-LDS B fragments, 4-stage cp.async.
// ---------------------------------------------------------------------------
#define BM 128
#define BN 128
#define BK2 16
#define AROW 20
#define BROW 136
#define STAGES 4
#define AS_STAGE (BM * AROW)
#define BS_STAGE (BK2 * BROW)
#define GEMM_SMEM ((STAGES * (AS_STAGE + BS_STAGE)) * 4)   // 75776 bytes

template<bool HALF_OUT>
__global__ void __launch_bounds__(128, 2)
gemm_f16(const uint32_t* __restrict__ A, const uint32_t* __restrict__ Wp,
         const float* __restrict__ bias, void* __restrict__ Cout,
         int N, int K2)
{
    extern __shared__ uint32_t sm[];
    uint32_t* AsBase = sm;
    uint32_t* BsBase = sm + STAGES * AS_STAGE;

    const int tid  = threadIdx.x;
    const int brow = blockIdx.y * BM;
    const int bcol = blockIdx.x * BN;

    const int lane = tid & 31;
    const int wid  = tid >> 5;
    const int g    = lane >> 2;
    const int tig  = lane & 3;
    const int wm   = wid & 1;
    const int wn   = wid >> 1;

    const uint32_t asU = smem_u32(AsBase);
    const uint32_t bsU = smem_u32(BsBase);

    float acc[4][8][4];
#pragma unroll
    for (int mt = 0; mt < 4; mt++)
#pragma unroll
        for (int nt = 0; nt < 8; nt++)
#pragma unroll
            for (int v = 0; v < 4; v++) acc[mt][nt][v] = 0.0f;

    const int KT = K2 / BK2;

    auto load_stage = [&](int st, int kt) {
        const uint32_t aD = asU + (uint32_t)(st * AS_STAGE * 4);
        const uint32_t bD = bsU + (uint32_t)(st * BS_STAGE * 4);
#pragma unroll
        for (int u = 0; u < 4; u++) {
            const int li = u * 128 + tid;
            const int r = li >> 2;
            const int c = (li & 3) * 4;
            cp16(aD + (uint32_t)((r * AROW + c) * 4),
                 A + (size_t)(brow + r) * K2 + kt * BK2 + c);
        }
#pragma unroll
        for (int u = 0; u < 4; u++) {
            const int li = u * 128 + tid;
            const int r = li >> 5;
            const int c = (li & 31) * 4;
            cp16(bD + (uint32_t)((r * BROW + c) * 4),
                 Wp + (size_t)(kt * BK2 + r) * N + bcol + c);
        }
    };

#pragma unroll
    for (int s = 0; s < STAGES - 1; s++) {
        load_stage(s, s);
        asm volatile("cp.async.commit_group;" ::: "memory");
    }

    const int lm_row  = lane & 15;
    const int lm_koff = (lane >> 4) << 2;

    for (int kt = 0; kt < KT; kt++) {
        const int cur = kt & (STAGES - 1);
        asm volatile("cp.async.wait_group 2;" ::: "memory");
        __syncthreads();

        if (kt + STAGES - 1 < KT)
            load_stage((kt + STAGES - 1) & (STAGES - 1), kt + STAGES - 1);
        asm volatile("cp.async.commit_group;" ::: "memory");

        const uint32_t  aStage = asU + (uint32_t)(cur * AS_STAGE * 4);
        const uint32_t* Bsu    = BsBase + cur * BS_STAGE;

#pragma unroll
        for (int kc = 0; kc < BK2; kc += 8) {
            uint32_t af[4][4], bf[8][2];
#pragma unroll
            for (int mt = 0; mt < 4; mt++) {
                const int r = wm * 64 + mt * 16 + lm_row;
                const uint32_t addr = aStage + (uint32_t)((r * AROW + kc + lm_koff) * 4);
                ldsm_x4(af[mt][0], af[mt][1], af[mt][2], af[mt][3], addr);
            }
#pragma unroll
            for (int nt = 0; nt < 8; nt++) {
                const int c0 = wn * 64 + nt * 8 + g;
                bf[nt][0] = Bsu[(kc + tig    ) * BROW + c0];
                bf[nt][1] = Bsu[(kc + tig + 4) * BROW + c0];
            }
#pragma unroll
            for (int mt = 0; mt < 4; mt++)
#pragma unroll
                for (int nt = 0; nt < 8; nt++)
                    mma_f16(acc[mt][nt][0], acc[mt][nt][1], acc[mt][nt][2], acc[mt][nt][3],
                            af[mt][0], af[mt][1], af[mt][2], af[mt][3],
                            bf[nt][0], bf[nt][1]);
        }
    }

    // ---- epilogue ----
#pragma unroll
    for (int nt = 0; nt < 8; nt++) {
        const int col = bcol + wn * 64 + nt * 8 + 2 * tig;
        const float b0 = bias[col];
        const float b1 = bias[col + 1];
#pragma unroll
        for (int mt = 0; mt < 4; mt++) {
            const int row0 = brow + wm * 64 + mt * 16 + g;
            if (HALF_OUT) {
                uint32_t* Ch = (uint32_t*)Cout;
                Ch[(size_t)row0 * (N / 2) + col / 2] =
                    pack_h2(acc[mt][nt][0] + b0, acc[mt][nt][1] + b1);
                Ch[(size_t)(row0 + 8) * (N / 2) + col / 2] =
                    pack_h2(acc[mt][nt][2] + b0, acc[mt][nt][3] + b1);
            } else {
                float* Cf = (float*)Cout;
                *(float2*)(Cf + (size_t)row0 * N + col) =
                    make_float2(acc[mt][nt][0] + b0, acc[mt][nt][1] + b1);
                *(float2*)(Cf + (size_t)(row0 + 8) * N + col) =
                    make_float2(acc[mt][nt][2] + b0, acc[mt][nt][3] + b1);
            }
        }
    }
}

// ---------------------------------------------------------------------------
// Fused prep: convert x -> half pairs; pack fc1_w, fc2_w pair-interleaved.
// ---------------------------------------------------------------------------
#define PREP_NX ((MROWS * CIN) / 4)
#define PREP_NP ((CIN / 2) * CH)

__global__ void __launch_bounds__(256)
prep_kernel(const float* __restrict__ x,
            const float* __restrict__ w1, const float* __restrict__ w2)
{
    const int i = blockIdx.x * 256 + threadIdx.x;
    if (i < PREP_NX) {
        float4 v = *(const float4*)(x + (size_t)i * 4);
        uint2 o;
        o.x = pack_h2(v.x, v.y);
        o.y = pack_h2(v.z, v.w);
        *(uint2*)(g_xh + (size_t)i * 2) = o;
    } else if (i < PREP_NX + PREP_NP) {
        const int j  = i - PREP_NX;
        const int k2 = j / CH;
        const int n  = j % CH;
        g_w1p[j] = pack_h2(w1[(size_t)(2 * k2) * CH + n],
                           w1[(size_t)(2 * k2 + 1) * CH + n]);
    } else if (i < PREP_NX + 2 * PREP_NP) {
        const int j  = i - PREP_NX - PREP_NP;
        const int k2 = j / CIN;
        const int n  = j % CIN;
        g_w2p[j] = pack_h2(w2[(size_t)(2 * k2) * CIN + n],
                           w2[(size_t)(2 * k2 + 1) * CIN + n]);
    }
}

// ---------------------------------------------------------------------------
// Depthwise 3x3 conv, chunked (256 tokens/CTA), half2 x 2 channels per lane.
// Grid (12 ccblocks, 21 chunks, 8 batches), block 256 = 32 ch2 x 8 slots.
// (R8 version — measured best.)
// ---------------------------------------------------------------------------
__global__ void __launch_bounds__(256)
dwconv_kernel(const float* __restrict__ dw_w, const float* __restrict__ dw_b)
{
    const int cc  = blockIdx.x;
    const int chk = blockIdx.y;
    const int b   = blockIdx.z;

    int s, cis;
    if (chk < 16)      { s = 0; cis = chk; }
    else if (chk < 20) { s = 1; cis = chk - 16; }
    else               { s = 2; cis = 0; }

    const int offs[3] = {0, 4096, 5120};
    const int lws[3]  = {6, 5, 4};
    const int off  = offs[s];
    const int lw   = lws[s];
    const int w    = 1 << lw;
    const int tok0 = cis * 256;

    const int tid   = threadIdx.x;
    const int lane  = tid & 31;
    const int tslot = tid >> 5;
    const int c2    = cc * 32 + lane;

    float wA[9], wB[9];
#pragma unroll
    for (int i = 0; i < 9; i++) {
        wA[i] = dw_w[(2 * c2)     * 9 + i];
        wB[i] = dw_w[(2 * c2 + 1) * 9 + i];
    }
    const float bkA = dw_b[2 * c2];
    const float bkB = dw_b[2 * c2 + 1];

    const __half2* base  = (const __half2*)g_h1h + (size_t)(b * NTOK + off) * (CH / 2) + c2;
    __half2*       obase = (__half2*)g_hch       + (size_t)(b * NTOK + off) * (CH / 2) + c2;

    float sA = 0.0f, sB = 0.0f;
    float mA = -INFINITY, mB = -INFINITY;

#pragma unroll 4
    for (int t = tslot; t < 256; t += 8) {
        const int tok = tok0 + t;
        const int y = tok >> lw;
        const int x = tok & (w - 1);
        float accA = bkA, accB = bkB;
#pragma unroll
        for (int ky = 0; ky < 3; ky++) {
            const int yy = y + ky - 1;
            if ((unsigned)yy < (unsigned)w) {
                const int rb = yy << lw;
#pragma unroll
                for (int kx = 0; kx < 3; kx++) {
                    const int xx = x + kx - 1;
                    if ((unsigned)xx < (unsigned)w) {
                        float2 v = __half22float2(base[(size_t)(rb + xx) * (CH / 2)]);
                        accA += wA[ky * 3 + kx] * v.x;
                        accB += wB[ky * 3 + kx] * v.y;
                    }
                }
            }
        }
        obase[(size_t)tok * (CH / 2)] = __floats2half2_rn(accA, accB);
        sA += accA; sB += accB;
        mA = fmaxf(mA, accA); mB = fmaxf(mB, accB);
    }

    __shared__ float2 ssum[256];
    __shared__ float2 smax[256];
    ssum[tid] = make_float2(sA, sB);
    smax[tid] = make_float2(mA, mB);
    __syncthreads();
    if (tslot == 0) {
        float tsA = sA, tsB = sB, tmA = mA, tmB = mB;
#pragma unroll
        for (int j = 1; j < 8; j++) {
            float2 v = ssum[j * 32 + lane];
            float2 m = smax[j * 32 + lane];
            tsA += v.x; tsB += v.y;
            tmA = fmaxf(tmA, m.x); tmB = fmaxf(tmB, m.y);
        }
        const size_t pb = ((size_t)b * NCHUNK + chk) * CH + 2 * c2;
        g_psum[pb]     = tsA;
        g_psum[pb + 1] = tsB;
        g_pmax[pb]     = tmA;
        g_pmax[pb + 1] = tmB;
    }
}

// ---------------------------------------------------------------------------
// Gate softmax + SE channel gates; reduces chunk partials.
// 768 threads (one per channel), one block per (s,b).  (R10 version, -5us.)
// ---------------------------------------------------------------------------
__global__ void __launch_bounds__(768)
gate_scale_kernel(const float* __restrict__ gate_w, const float* __restrict__ gate_b,
                  const float* __restrict__ ca_w,   const float* __restrict__ ra_w)
{
    const int sb  = blockIdx.x;
    const int s   = sb >> 3;
    const int b   = sb & 7;
    const int c   = threadIdx.x;

    const int cs   = (s == 0) ? 0 : (s == 1) ? 16 : 20;
    const int nch  = (s == 0) ? 16 : (s == 1) ? 4 : 1;
    const int ntok = (s == 0) ? 4096 : (s == 1) ? 1024 : 256;

    __shared__ float pool[CH + 2];
    __shared__ float red0[768];
    __shared__ float red1[768];
    __shared__ float gw0s, gw1s;

    const size_t pb0 = ((size_t)b * NCHUNK + cs) * CH + c;
    float sum = 0.0f, mx = -INFINITY;
#pragma unroll 4
    for (int j = 0; j < nch; j++) {
        sum += g_psum[pb0 + (size_t)j * CH];
        mx = fmaxf(mx, g_pmax[pb0 + (size_t)j * CH]);
    }
    const float a = sum / (float)ntok;
    pool[c + 1] = a + mx;
    red0[c] = a * gate_w[c * 2 + 0];
    red1[c] = a * gate_w[c * 2 + 1];
    if (c == 0) { pool[0] = 0.0f; pool[CH + 1] = 0.0f; }
    __syncthreads();

    for (int sft = 512; sft > 0; sft >>= 1) {
        if (c < sft && c + sft < CH) {
            red0[c] += red0[c + sft];
            red1[c] += red1[c + sft];
        }
        __syncthreads();
    }
    if (c == 0) {
        const float l0 = red0[0] + gate_b[0];
        const float l1 = red1[0] + gate_b[1];
        const float m  = fmaxf(l0, l1);
        const float e0 = expf(l0 - m), e1 = expf(l1 - m);
        const float inv = 1.0f / (e0 + e1);
        gw0s = e0 * inv;
        gw1s = e1 * inv;
    }
    __syncthreads();

    const float c0 = ca_w[0], c1 = ca_w[1], c2 = ca_w[2];
    const float r0 = ra_w[0], r1 = ra_w[1], r2 = ra_w[2];
    const float pm = pool[c], pc = pool[c + 1], pp = pool[c + 2];
    const float cav = c0 * pm + c1 * pc + c2 * pp;
    const float rav = r0 * pm + r1 * pc + r2 * pp;
    const float cas = 1.0f / (1.0f + expf(-cav));
    const float ras = 1.0f - 1.0f / (1.0f + expf(-rav));
    g_scale[sb * CH + c] = gw0s * cas + gw1s * ras;
}

// ---------------------------------------------------------------------------
// Elementwise in place on g_hch: h <- half(gelu_exact(h * scale)), uint4/thread
// ---------------------------------------------------------------------------
__device__ __forceinline__ float gelu_exact(float v)
{
    return 0.5f * v * (1.0f + erff(v * 0.70710678118654752440f));
}

__global__ void __launch_bounds__(256)
gelu_scale_kernel()
{
    const size_t nvec = (size_t)MROWS * CH / 8;
    const size_t i = (size_t)blockIdx.x * blockDim.x + threadIdx.x;
    if (i >= nvec) return;
    const size_t e   = i * 8;
    const int    row = (int)(e / CH);
    const int    c   = (int)(e % CH);
    const int    b   = row / NTOK;
    const int    tok = row % NTOK;
    const int    s   = (tok < 4096) ? 0 : ((tok < 5120) ? 1 : 2);

    uint4 hv = *((uint4*)g_hch + i);
    const float* sp = g_scale + (s * 8 + b) * CH + c;
    float4 sc0 = *(const float4*)sp;
    float4 sc1 = *(const float4*)(sp + 4);

    float2 v0 = __half22float2(*(__half2*)&hv.x);
    float2 v1 = __half22float2(*(__half2*)&hv.y);
    float2 v2 = __half22float2(*(__half2*)&hv.z);
    float2 v3 = __half22float2(*(__half2*)&hv.w);
    uint4 o;
    o.x = pack_h2(gelu_exact(v0.x * sc0.x), gelu_exact(v0.y * sc0.y));
    o.y = pack_h2(gelu_exact(v1.x * sc0.z), gelu_exact(v1.y * sc0.w));
    o.z = pack_h2(gelu_exact(v2.x * sc1.x), gelu_exact(v2.y * sc1.y));
    o.w = pack_h2(gelu_exact(v3.x * sc1.z), gelu_exact(v3.y * sc1.w));
    *((uint4*)g_hch + i) = o;
}

// ---------------------------------------------------------------------------
// Entry point
// ---------------------------------------------------------------------------
extern "C" void kernel_launch(void* const* d_in, const int* in_sizes, int n_in,
                              void* d_out, int out_size)
{
    const float* x      = (const float*)d_in[0];
    const float* fc1_w  = (const float*)d_in[1];
    const float* fc1_b  = (const float*)d_in[2];
    const float* dw_w   = (const float*)d_in[3];
    const float* dw_b   = (const float*)d_in[4];
    const float* ca_w   = (const float*)d_in[5];
    const float* ra_w   = (const float*)d_in[6];
    const float* gate_w = (const float*)d_in[7];
    const float* gate_b = (const float*)d_in[8];
    const float* fc2_w  = (const float*)d_in[9];
    const float* fc2_b  = (const float*)d_in[10];
    float* out = (float*)d_out;

    uint32_t *xh, *w1p, *w2p;
    __half *h1h, *hch;
    cudaGetSymbolAddress((void**)&xh,  g_xh);
    cudaGetSymbolAddress((void**)&h1h, g_h1h);
    cudaGetSymbolAddress((void**)&hch, g_hch);
    cudaGetSymbolAddress((void**)&w1p, g_w1p);
    cudaGetSymbolAddress((void**)&w2p, g_w2p);

    cudaFuncSetAttribute(gemm_f16<true>,  cudaFuncAttributeMaxDynamicSharedMemorySize, GEMM_SMEM);
    cudaFuncSetAttribute(gemm_f16<false>, cudaFuncAttributeMaxDynamicSharedMemorySize, GEMM_SMEM);

    // fused prep: convert x + pack both weights
    const int prep_total = PREP_NX + 2 * PREP_NP;
    prep_kernel<<<(prep_total + 255) / 256, 256>>>(x, fc1_w, fc2_w);

    // fc1: (43008 x 384) @ (384 x 768) -> g_h1h (half)
    gemm_f16<true><<<dim3(CH / BN, MROWS / BM), 128, GEMM_SMEM>>>(
        xh, w1p, fc1_b, h1h, CH, CIN / 2);

    // depthwise conv + chunked pooled stats (2 channels/lane, 2016 CTAs)
    dwconv_kernel<<<dim3(CH / 64, NCHUNK, BB), 256>>>(dw_w, dw_b);

    // gate softmax + SE channel gates (768 threads/block)
    gate_scale_kernel<<<24, 768>>>(gate_w, gate_b, ca_w, ra_w);

    // scale + exact GELU, in place on g_hch
    const size_t nvec = (size_t)MROWS * CH / 8;
    gelu_scale_kernel<<<(unsigned)((nvec + 255) / 256), 256>>>();

    // fc2: (43008 x 768) @ (768 x 384) + bias -> out (fp32)
    gemm_f16<false><<<dim3(CIN / BN, MROWS / BM), 128, GEMM_SMEM>>>(
        (const uint32_t*)hch, w2p, fc2_b, out, CIN, CH / 2);
}

// round 12
// speedup vs baseline: 1.3166x; 1.1520x over previous
#include <cuda_runtime.h>
#include <cuda_fp16.h>
#include <math.h>
#include <stdint.h>

// ---------------------------------------------------------------------------
// Problem constants (B=8, N=5376, Cin=384, Ch=768, H=W=32, n=256)
// ---------------------------------------------------------------------------
#define BB      8
#define NTOK    5376
#define CIN     384
#define CH      768
#define MROWS   (BB * NTOK)          // 43008
#define NCHUNK  21                   // 16 (s0) + 4 (s1) + 1 (s2), 256 tokens each

// ---------------------------------------------------------------------------
// Scratch (device globals; no runtime allocation)
// ---------------------------------------------------------------------------
__device__ uint32_t g_xh [(size_t)MROWS * CIN / 2];   // x as half pairs along K
__device__ __half   g_h1h[(size_t)MROWS * CH];        // fc1 output, half
__device__ __half   g_hch[(size_t)MROWS * CH];        // dwconv out -> gelu'd in place
__device__ uint32_t g_w1p[(CIN / 2) * CH];            // fc1_w pair-interleaved [k2][n]
__device__ uint32_t g_w2p[(CH / 2) * CIN];            // fc2_w pair-interleaved [k2][n]
__device__ float    g_psum[BB * NCHUNK * CH];
__device__ float    g_pmax[BB * NCHUNK * CH];
__device__ float    g_scale[24 * CH];

// ---------------------------------------------------------------------------
// Helpers
// ---------------------------------------------------------------------------
__device__ __forceinline__ uint32_t smem_u32(const void* p) {
    uint32_t a;
    asm("{ .reg .u64 t; cvta.to.shared.u64 t, %1; cvt.u32.u64 %0, t; }"
        : "=r"(a) : "l"(p));
    return a;
}
__device__ __forceinline__ void cp16(uint32_t d, const void* s) {
    asm volatile("cp.async.cg.shared.global [%0], [%1], 16;\n" :: "r"(d), "l"(s));
}
__device__ __forceinline__ uint32_t pack_h2(float a, float b) {
    __half2 h = __floats2half2_rn(a, b);
    return *(uint32_t*)&h;
}
__device__ __forceinline__ void mma_f16(float& d0, float& d1, float& d2, float& d3,
                                        uint32_t a0, uint32_t a1, uint32_t a2, uint32_t a3,
                                        uint32_t b0, uint32_t b1) {
    asm volatile(
        "mma.sync.aligned.m16n8k16.row.col.f32.f16.f16.f32 "
        "{%0,%1,%2,%3}, {%4,%5,%6,%7}, {%8,%9}, {%0,%1,%2,%3};\n"
        : "+f"(d0), "+f"(d1), "+f"(d2), "+f"(d3)
        : "r"(a0), "r"(a1), "r"(a2), "r"(a3), "r"(b0), "r"(b1));
}
__device__ __forceinline__ void ldsm_x4(uint32_t& r0, uint32_t& r1,
                                        uint32_t& r2, uint32_t& r3, uint32_t addr) {
    asm volatile("ldmatrix.sync.aligned.m8n8.x4.shared.b16 {%0,%1,%2,%3}, [%4];"
                 : "=r"(r0), "=r"(r1), "=r"(r2), "=r"(r3) : "r"(addr));
}

// ---------------------------------------------------------------------------
// FP16 GEMM (R8 config, proven): C = A @ W + bias, fp32 accum.
// 128 threads (4 warps 2x2), warp tile 64x64, BM=BN=128, BK2=16 (K=32),
// ldmatrix.x4 A-fragments, scalar-LDS B fragments, 4-stage cp.async.
// ---------------------------------------------------------------------------
#define BM 128
#define BN 128
#define BK2 16
#define AROW 20
#define BROW 136
#define STAGES 4
#define AS_STAGE (BM * AROW)
#define BS_STAGE (BK2 * BROW)
#define GEMM_SMEM ((STAGES * (AS_STAGE + BS_STAGE)) * 4)   // 75776 bytes

template<bool HALF_OUT>
__global__ void __launch_bounds__(128, 2)
gemm_f16(const uint32_t* __restrict__ A, const uint32_t* __restrict__ Wp,
         const float* __restrict__ bias, void* __restrict__ Cout,
         int N, int K2)
{
    extern __shared__ uint32_t sm[];
    uint32_t* AsBase = sm;
    uint32_t* BsBase = sm + STAGES * AS_STAGE;

    const int tid  = threadIdx.x;
    const int brow = blockIdx.y * BM;
    const int bcol = blockIdx.x * BN;

    const int lane = tid & 31;
    const int wid  = tid >> 5;
    const int g    = lane >> 2;
    const int tig  = lane & 3;
    const int wm   = wid & 1;
    const int wn   = wid >> 1;

    const uint32_t asU = smem_u32(AsBase);
    const uint32_t bsU = smem_u32(BsBase);

    float acc[4][8][4];
#pragma unroll
    for (int mt = 0; mt < 4; mt++)
#pragma unroll
        for (int nt = 0; nt < 8; nt++)
#pragma unroll
            for (int v = 0; v < 4; v++) acc[mt][nt][v] = 0.0f;

    const int KT = K2 / BK2;

    auto load_stage = [&](int st, int kt) {
        const uint32_t aD = asU + (uint32_t)(st * AS_STAGE * 4);
        const uint32_t bD = bsU + (uint32_t)(st * BS_STAGE * 4);
#pragma unroll
        for (int u = 0; u < 4; u++) {
            const int li = u * 128 + tid;
            const int r = li >> 2;
            const int c = (li & 3) * 4;
            cp16(aD + (uint32_t)((r * AROW + c) * 4),
                 A + (size_t)(brow + r) * K2 + kt * BK2 + c);
        }
#pragma unroll
        for (int u = 0; u < 4; u++) {
            const int li = u * 128 + tid;
            const int r = li >> 5;
            const int c = (li & 31) * 4;
            cp16(bD + (uint32_t)((r * BROW + c) * 4),
                 Wp + (size_t)(kt * BK2 + r) * N + bcol + c);
        }
    };

#pragma unroll
    for (int s = 0; s < STAGES - 1; s++) {
        load_stage(s, s);
        asm volatile("cp.async.commit_group;" ::: "memory");
    }

    const int lm_row  = lane & 15;
    const int lm_koff = (lane >> 4) << 2;

    for (int kt = 0; kt < KT; kt++) {
        const int cur = kt & (STAGES - 1);
        asm volatile("cp.async.wait_group 2;" ::: "memory");
        __syncthreads();

        if (kt + STAGES - 1 < KT)
            load_stage((kt + STAGES - 1) & (STAGES - 1), kt + STAGES - 1);
        asm volatile("cp.async.commit_group;" ::: "memory");

        const uint32_t  aStage = asU + (uint32_t)(cur * AS_STAGE * 4);
        const uint32_t* Bsu    = BsBase + cur * BS_STAGE;

#pragma unroll
        for (int kc = 0; kc < BK2; kc += 8) {
            uint32_t af[4][4], bf[8][2];
#pragma unroll
            for (int mt = 0; mt < 4; mt++) {
                const int r = wm * 64 + mt * 16 + lm_row;
                const uint32_t addr = aStage + (uint32_t)((r * AROW + kc + lm_koff) * 4);
                ldsm_x4(af[mt][0], af[mt][1], af[mt][2], af[mt][3], addr);
            }
#pragma unroll
            for (int nt = 0; nt < 8; nt++) {
                const int c0 = wn * 64 + nt * 8 + g;
                bf[nt][0] = Bsu[(kc + tig    ) * BROW + c0];
                bf[nt][1] = Bsu[(kc + tig + 4) * BROW + c0];
            }
#pragma unroll
            for (int mt = 0; mt < 4; mt++)
#pragma unroll
                for (int nt = 0; nt < 8; nt++)
                    mma_f16(acc[mt][nt][0], acc[mt][nt][1], acc[mt][nt][2], acc[mt][nt][3],
                            af[mt][0], af[mt][1], af[mt][2], af[mt][3],
                            bf[nt][0], bf[nt][1]);
        }
    }

    // ---- epilogue ----
#pragma unroll
    for (int nt = 0; nt < 8; nt++) {
        const int col = bcol + wn * 64 + nt * 8 + 2 * tig;
        const float b0 = bias[col];
        const float b1 = bias[col + 1];
#pragma unroll
        for (int mt = 0; mt < 4; mt++) {
            const int row0 = brow + wm * 64 + mt * 16 + g;
            if (HALF_OUT) {
                uint32_t* Ch = (uint32_t*)Cout;
                Ch[(size_t)row0 * (N / 2) + col / 2] =
                    pack_h2(acc[mt][nt][0] + b0, acc[mt][nt][1] + b1);
                Ch[(size_t)(row0 + 8) * (N / 2) + col / 2] =
                    pack_h2(acc[mt][nt][2] + b0, acc[mt][nt][3] + b1);
            } else {
                float* Cf = (float*)Cout;
                *(float2*)(Cf + (size_t)row0 * N + col) =
                    make_float2(acc[mt][nt][0] + b0, acc[mt][nt][1] + b1);
                *(float2*)(Cf + (size_t)(row0 + 8) * N + col) =
                    make_float2(acc[mt][nt][2] + b0, acc[mt][nt][3] + b1);
            }
        }
    }
}

// ---------------------------------------------------------------------------
// Fused prep: convert x -> half pairs; pack fc1_w, fc2_w pair-interleaved.
// ---------------------------------------------------------------------------
#define PREP_NX ((MROWS * CIN) / 4)
#define PREP_NP ((CIN / 2) * CH)

__global__ void __launch_bounds__(256)
prep_kernel(const float* __restrict__ x,
            const float* __restrict__ w1, const float* __restrict__ w2)
{
    const int i = blockIdx.x * 256 + threadIdx.x;
    if (i < PREP_NX) {
        float4 v = *(const float4*)(x + (size_t)i * 4);
        uint2 o;
        o.x = pack_h2(v.x, v.y);
        o.y = pack_h2(v.z, v.w);
        *(uint2*)(g_xh + (size_t)i * 2) = o;
    } else if (i < PREP_NX + PREP_NP) {
        const int j  = i - PREP_NX;
        const int k2 = j / CH;
        const int n  = j % CH;
        g_w1p[j] = pack_h2(w1[(size_t)(2 * k2) * CH + n],
                           w1[(size_t)(2 * k2 + 1) * CH + n]);
    } else if (i < PREP_NX + 2 * PREP_NP) {
        const int j  = i - PREP_NX - PREP_NP;
        const int k2 = j / CIN;
        const int n  = j % CIN;
        g_w2p[j] = pack_h2(w2[(size_t)(2 * k2) * CIN + n],
                           w2[(size_t)(2 * k2 + 1) * CIN + n]);
    }
}

// ---------------------------------------------------------------------------
// Depthwise 3x3 conv, chunked (256 tokens/CTA), 2 channels/lane, SMEM-tiled:
// the CTA's 64-channel slice of the chunk + one halo row is staged in shared
// memory (zero-filled outside the map), taps come from LDS instead of 9
// strided GMEM loads. Accumulation order identical to the untiled version.
// Grid (12, 21, 8), block 256 = 32 half2-lanes x 8 token-slots.
// Dynamic smem: 384*32 half2 tile (48KB) + 2*256 float2 reductions (4KB).
// ---------------------------------------------------------------------------
#define DW_TILE_MAX (384 * 32)                         // half2 slots (s0 region)
#define DW_SMEM (DW_TILE_MAX * 4 + 2 * 256 * 8)        // 53248 bytes

__global__ void __launch_bounds__(256)
dwconv_kernel(const float* __restrict__ dw_w, const float* __restrict__ dw_b)
{
    extern __shared__ char dsm[];
    __half2* tile = (__half2*)dsm;
    float2*  ssum = (float2*)(dsm + DW_TILE_MAX * 4);
    float2*  smax = ssum + 256;

    const int cc  = blockIdx.x;
    const int chk = blockIdx.y;
    const int b   = blockIdx.z;

    int s, cis;
    if (chk < 16)      { s = 0; cis = chk; }
    else if (chk < 20) { s = 1; cis = chk - 16; }
    else               { s = 2; cis = 0; }

    const int offs[3] = {0, 4096, 5120};
    const int lws[3]  = {6, 5, 4};
    const int off  = offs[s];
    const int lw   = lws[s];
    const int w    = 1 << lw;
    const int nmap = w * w;
    const int tok0 = cis * 256;
    const int region = 256 + 2 * w;      // chunk + halo row each side

    const int tid   = threadIdx.x;
    const int lane  = tid & 31;
    const int tslot = tid >> 5;
    const int c2    = cc * 32 + lane;

    // ---- stage tile: region tokens x 32 half2, zero outside map ----
    {
        const uint4* grow = (const uint4*)((const __half2*)g_h1h
                            + (size_t)(b * NTOK + off) * (CH / 2) + cc * 32);
        const int nvec = region * 8;     // 8 uint4 per token row of 32 half2
        for (int i = tid; i < nvec; i += 256) {
            const int t = i >> 3;
            const int p = i & 7;
            const int g_tok = tok0 - w + t;
            uint4 v = make_uint4(0u, 0u, 0u, 0u);
            if ((unsigned)g_tok < (unsigned)nmap)
                v = grow[(size_t)g_tok * (CH / 8) + p];   // CH/2 half2 = CH/8 uint4
            *(uint4*)(tile + t * 32 + p * 4) = v;
        }
    }
    __syncthreads();

    float wA[9], wB[9];
#pragma unroll
    for (int i = 0; i < 9; i++) {
        wA[i] = dw_w[(2 * c2)     * 9 + i];
        wB[i] = dw_w[(2 * c2 + 1) * 9 + i];
    }
    const float bkA = dw_b[2 * c2];
    const float bkB = dw_b[2 * c2 + 1];

    __half2* obase = (__half2*)g_hch + (size_t)(b * NTOK + off) * (CH / 2) + c2;

    float sA = 0.0f, sB = 0.0f;
    float mA = -INFINITY, mB = -INFINITY;

#pragma unroll 4
    for (int t = tslot; t < 256; t += 8) {
        const int tok = tok0 + t;
        const int x  = tok & (w - 1);
        const int tc = t + w;            // center token in region coords
        float accA = bkA, accB = bkB;
#pragma unroll
        for (int ky = 0; ky < 3; ky++) {
            const int rb = tc + (ky - 1) * w;   // row halo is zero-filled
#pragma unroll
            for (int kx = 0; kx < 3; kx++) {
                const int xx = x + kx - 1;
                if ((unsigned)xx < (unsigned)w) {
                    float2 v = __half22float2(tile[(rb + kx - 1) * 32 + lane]);
                    accA += wA[ky * 3 + kx] * v.x;
                    accB += wB[ky * 3 + kx] * v.y;
                }
            }
        }
        obase[(size_t)tok * (CH / 2)] = __floats2half2_rn(accA, accB);
        sA += accA; sB += accB;
        mA = fmaxf(mA, accA); mB = fmaxf(mB, accB);
    }

    ssum[tid] = make_float2(sA, sB);
    smax[tid] = make_float2(mA, mB);
    __syncthreads();
    if (tslot == 0) {
        float tsA = sA, tsB = sB, tmA = mA, tmB = mB;
#pragma unroll
        for (int j = 1; j < 8; j++) {
            float2 v = ssum[j * 32 + lane];
            float2 m = smax[j * 32 + lane];
            tsA += v.x; tsB += v.y;
            tmA = fmaxf(tmA, m.x); tmB = fmaxf(tmB, m.y);
        }
        const size_t pb = ((size_t)b * NCHUNK + chk) * CH + 2 * c2;
        g_psum[pb]     = tsA;
        g_psum[pb + 1] = tsB;
        g_pmax[pb]     = tmA;
        g_pmax[pb + 1] = tmB;
    }
}

// ---------------------------------------------------------------------------
// Gate softmax + SE channel gates; reduces chunk partials.
// 768 threads (one per channel), one block per (s,b).
// ---------------------------------------------------------------------------
__global__ void __launch_bounds__(768)
gate_scale_kernel(const float* __restrict__ gate_w, const float* __restrict__ gate_b,
                  const float* __restrict__ ca_w,   const float* __restrict__ ra_w)
{
    const int sb  = blockIdx.x;
    const int s   = sb >> 3;
    const int b   = sb & 7;
    const int c   = threadIdx.x;

    const int cs   = (s == 0) ? 0 : (s == 1) ? 16 : 20;
    const int nch  = (s == 0) ? 16 : (s == 1) ? 4 : 1;
    const int ntok = (s == 0) ? 4096 : (s == 1) ? 1024 : 256;

    __shared__ float pool[CH + 2];
    __shared__ float red0[768];
    __shared__ float red1[768];
    __shared__ float gw0s, gw1s;

    const size_t pb0 = ((size_t)b * NCHUNK + cs) * CH + c;
    float sum = 0.0f, mx = -INFINITY;
#pragma unroll 4
    for (int j = 0; j < nch; j++) {
        sum += g_psum[pb0 + (size_t)j * CH];
        mx = fmaxf(mx, g_pmax[pb0 + (size_t)j * CH]);
    }
    const float a = sum / (float)ntok;
    pool[c + 1] = a + mx;
    red0[c] = a * gate_w[c * 2 + 0];
    red1[c] = a * gate_w[c * 2 + 1];
    if (c == 0) { pool[0] = 0.0f; pool[CH + 1] = 0.0f; }
    __syncthreads();

    for (int sft = 512; sft > 0; sft >>= 1) {
        if (c < sft && c + sft < CH) {
            red0[c] += red0[c + sft];
            red1[c] += red1[c + sft];
        }
        __syncthreads();
    }
    if (c == 0) {
        const float l0 = red0[0] + gate_b[0];
        const float l1 = red1[0] + gate_b[1];
        const float m  = fmaxf(l0, l1);
        const float e0 = expf(l0 - m), e1 = expf(l1 - m);
        const float inv = 1.0f / (e0 + e1);
        gw0s = e0 * inv;
        gw1s = e1 * inv;
    }
    __syncthreads();

    const float c0 = ca_w[0], c1 = ca_w[1], c2 = ca_w[2];
    const float r0 = ra_w[0], r1 = ra_w[1], r2 = ra_w[2];
    const float pm = pool[c], pc = pool[c + 1], pp = pool[c + 2];
    const float cav = c0 * pm + c1 * pc + c2 * pp;
    const float rav = r0 * pm + r1 * pc + r2 * pp;
    const float cas = 1.0f / (1.0f + expf(-cav));
    const float ras = 1.0f - 1.0f / (1.0f + expf(-rav));
    g_scale[sb * CH + c] = gw0s * cas + gw1s * ras;
}

// ---------------------------------------------------------------------------
// Elementwise in place on g_hch: h <- half(gelu_exact(h * scale)), uint4/thread
// ---------------------------------------------------------------------------
__device__ __forceinline__ float gelu_exact(float v)
{
    return 0.5f * v * (1.0f + erff(v * 0.70710678118654752440f));
}

__global__ void __launch_bounds__(256)
gelu_scale_kernel()
{
    const size_t nvec = (size_t)MROWS * CH / 8;
    const size_t i = (size_t)blockIdx.x * blockDim.x + threadIdx.x;
    if (i >= nvec) return;
    const size_t e   = i * 8;
    const int    row = (int)(e / CH);
    const int    c   = (int)(e % CH);
    const int    b   = row / NTOK;
    const int    tok = row % NTOK;
    const int    s   = (tok < 4096) ? 0 : ((tok < 5120) ? 1 : 2);

    uint4 hv = *((uint4*)g_hch + i);
    const float* sp = g_scale + (s * 8 + b) * CH + c;
    float4 sc0 = *(const float4*)sp;
    float4 sc1 = *(const float4*)(sp + 4);

    float2 v0 = __half22float2(*(__half2*)&hv.x);
    float2 v1 = __half22float2(*(__half2*)&hv.y);
    float2 v2 = __half22float2(*(__half2*)&hv.z);
    float2 v3 = __half22float2(*(__half2*)&hv.w);
    uint4 o;
    o.x = pack_h2(gelu_exact(v0.x * sc0.x), gelu_exact(v0.y * sc0.y));
    o.y = pack_h2(gelu_exact(v1.x * sc0.z), gelu_exact(v1.y * sc0.w));
    o.z = pack_h2(gelu_exact(v2.x * sc1.x), gelu_exact(v2.y * sc1.y));
    o.w = pack_h2(gelu_exact(v3.x * sc1.z), gelu_exact(v3.y * sc1.w));
    *((uint4*)g_hch + i) = o;
}

// ---------------------------------------------------------------------------
// Entry point
// ---------------------------------------------------------------------------
extern "C" void kernel_launch(void* const* d_in, const int* in_sizes, int n_in,
                              void* d_out, int out_size)
{
    const float* x      = (const float*)d_in[0];
    const float* fc1_w  = (const float*)d_in[1];
    const float* fc1_b  = (const float*)d_in[2];
    const float* dw_w   = (const float*)d_in[3];
    const float* dw_b   = (const float*)d_in[4];
    const float* ca_w   = (const float*)d_in[5];
    const float* ra_w   = (const float*)d_in[6];
    const float* gate_w = (const float*)d_in[7];
    const float* gate_b = (const float*)d_in[8];
    const float* fc2_w  = (const float*)d_in[9];
    const float* fc2_b  = (const float*)d_in[10];
    float* out = (float*)d_out;

    uint32_t *xh, *w1p, *w2p;
    __half *h1h, *hch;
    cudaGetSymbolAddress((void**)&xh,  g_xh);
    cudaGetSymbolAddress((void**)&h1h, g_h1h);
    cudaGetSymbolAddress((void**)&hch, g_hch);
    cudaGetSymbolAddress((void**)&w1p, g_w1p);
    cudaGetSymbolAddress((void**)&w2p, g_w2p);

    cudaFuncSetAttribute(gemm_f16<true>,  cudaFuncAttributeMaxDynamicSharedMemorySize, GEMM_SMEM);
    cudaFuncSetAttribute(gemm_f16<false>, cudaFuncAttributeMaxDynamicSharedMemorySize, GEMM_SMEM);
    cudaFuncSetAttribute(dwconv_kernel,   cudaFuncAttributeMaxDynamicSharedMemorySize, DW_SMEM);

    // fused prep: convert x + pack both weights
    const int prep_total = PREP_NX + 2 * PREP_NP;
    prep_kernel<<<(prep_total + 255) / 256, 256>>>(x, fc1_w, fc2_w);

    // fc1: (43008 x 384) @ (384 x 768) -> g_h1h (half)
    gemm_f16<true><<<dim3(CH / BN, MROWS / BM), 128, GEMM_SMEM>>>(
        xh, w1p, fc1_b, h1h, CH, CIN / 2);

    // depthwise conv + chunked pooled stats (smem-tiled)
    dwconv_kernel<<<dim3(CH / 64, NCHUNK, BB), 256, DW_SMEM>>>(dw_w, dw_b);

    // gate softmax + SE channel gates (768 threads/block)
    gate_scale_kernel<<<24, 768>>>(gate_w, gate_b, ca_w, ra_w);

    // scale + exact GELU, in place on g_hch
    const size_t nvec = (size_t)MROWS * CH / 8;
    gelu_scale_kernel<<<(unsigned)((nvec + 255) / 256), 256>>>();

    // fc2: (43008 x 768) @ (768 x 384) + bias -> out (fp32)
    gemm_f16<false><<<dim3(CIN / BN, MROWS / BM), 128, GEMM_SMEM>>>(
        (const uint32_t*)hch, w2p, fc2_b, out, CIN, CH / 2);
}